// round 10
// baseline (speedup 1.0000x reference)
#include <cuda_runtime.h>
#include <cuda_fp16.h>
#include <math.h>
#include <stdint.h>

#define NN 100000
#define CC 128
#define EE 600000
#define HH 64
#define TILE 128
#define NTILES ((EE + TILE - 1) / TILE)   // 4688 (last tile half)
#define MAIN_GRID 608                      // 152 SMs * 4 — exactly resident
#define MAIN_THREADS 256
#define PREP_UNITS (NN * CC / 8)           // 1.6M 8-channel units

#define APW 68                  // A pitch in 32-bit words (fp16x2 units): 64 + 4 pad

// SMEM float offsets
#define OFF_A   0               // 128*68 = 8704 words
#define OFF_BP  8704            // packed B frags: 8*4*32 uint4 = 4096 words
#define OFF_B1  12800           // 64
#define OFF_W2  12864           // 64
#define OFF_RED 12928           // 8 warps * 32 partials = 256
#define SMEM_FLOATS 13184       // 52736 bytes -> 4 blocks/SM (211KB)

// Node tables in fp16: v1 = z_out + z_self, v2 = z_in + z_self (25.6 MB each).
__device__ uint4 g_v1h[(size_t)NN * CC / 8];
__device__ uint4 g_v2h[(size_t)NN * CC / 8];
__device__ unsigned int g_bar_ctr;   // zero-init; monotonic across graph replays

__device__ __forceinline__ uint32_t f2h2(float lo, float hi) {
    uint32_t r;
    asm("cvt.rn.f16x2.f32 %0, %1, %2;" : "=r"(r) : "f"(hi), "f"(lo));
    return r;
}

__device__ __forceinline__ void mma_f16(float* c,
                                        uint32_t a0, uint32_t a1, uint32_t a2, uint32_t a3,
                                        uint32_t b0, uint32_t b1) {
    asm volatile(
        "mma.sync.aligned.m16n8k16.row.col.f32.f16.f16.f32 "
        "{%0,%1,%2,%3}, {%4,%5,%6,%7}, {%8,%9}, {%0,%1,%2,%3};"
        : "+f"(c[0]), "+f"(c[1]), "+f"(c[2]), "+f"(c[3])
        : "r"(a0), "r"(a1), "r"(a2), "r"(a3), "r"(b0), "r"(b1));
}

// ONE persistent kernel:
//   phase 1: grid-strided prep (fp32 -> fp16 node tables) + weight staging
//   software grid barrier (grid == resident block count, so deadlock-free)
//   phase 2: fused gather + fp16 mma GEMM + ELU + GEMV + sigmoid (R9 design)
__global__ __launch_bounds__(MAIN_THREADS, 4)
void fused_kernel(const float* __restrict__ z_in,
                  const float* __restrict__ z_out,
                  const float* __restrict__ z_self,
                  const int* __restrict__ eidx,
                  const float* __restrict__ W1,
                  const float* __restrict__ b1,
                  const float* __restrict__ W2,
                  const float* __restrict__ b2,
                  float* __restrict__ out)
{
    extern __shared__ float smem[];
    uint32_t* Au  = (uint32_t*)(smem + OFF_A);
    uint4*    Bp  = (uint4*)(smem + OFF_BP);
    float*    b1s = smem + OFF_B1;
    float*    w2s = smem + OFF_W2;
    float*    red = smem + OFF_RED;

    const int tid   = threadIdx.x;
    const int lane  = tid & 31;
    const int warp  = tid >> 5;
    const int gid   = lane >> 2;   // 0..7
    const int tig   = lane & 3;    // 0..3
    const int wb    = warp * 16;   // gather row base (16 edges per warp)
    const int lw    = lane & 15;
    const int pair  = warp >> 1;   // 0..3
    const int nhalf = warp & 1;    // n-half: 0 -> cols 0..31, 1 -> 32..63
    const int pb    = pair * 32;   // pair's edge-row base within tile
    const int barid = pair + 1;

    // ================= Phase 1: prep (grid-strided, HBM-bound) =================
    {
        const float4* zi = (const float4*)z_in;
        const float4* zo = (const float4*)z_out;
        const float4* zs = (const float4*)z_self;
        for (int i = blockIdx.x * MAIN_THREADS + tid; i < PREP_UNITS;
             i += MAIN_GRID * MAIN_THREADS) {
            const float4 s0 = zs[2 * i], s1 = zs[2 * i + 1];
            const float4 a0 = zo[2 * i], a1 = zo[2 * i + 1];
            const float4 b0 = zi[2 * i], b1v = zi[2 * i + 1];
            uint4 o1, o2;
            o1.x = f2h2(a0.x + s0.x, a0.y + s0.y);
            o1.y = f2h2(a0.z + s0.z, a0.w + s0.w);
            o1.z = f2h2(a1.x + s1.x, a1.y + s1.y);
            o1.w = f2h2(a1.z + s1.z, a1.w + s1.w);
            o2.x = f2h2(b0.x + s0.x, b0.y + s0.y);
            o2.y = f2h2(b0.z + s0.z, b0.w + s0.w);
            o2.z = f2h2(b1v.x + s1.x, b1v.y + s1.y);
            o2.w = f2h2(b1v.z + s1.z, b1v.w + s1.w);
            g_v1h[i] = o1;
            g_v2h[i] = o2;
        }
    }

    // ---- Weight staging (independent of prep; overlaps other blocks' tail) ----
    for (int i = tid; i < 8 * 4 * 32; i += MAIN_THREADS) {
        const int l   = i & 31;
        const int nt2 = (i >> 5) & 3;
        const int ks  = i >> 7;
        const int g   = l >> 2;
        const int t   = l & 3;
        const int k0  = ks * 16;
        const int n0  = nt2 * 16 + g;
        const int n1  = n0 + 8;
        uint4 v;
        v.x = f2h2(W1[(k0 + 2 * t) * HH + n0],     W1[(k0 + 2 * t + 1) * HH + n0]);
        v.y = f2h2(W1[(k0 + 2 * t + 8) * HH + n0], W1[(k0 + 2 * t + 9) * HH + n0]);
        v.z = f2h2(W1[(k0 + 2 * t) * HH + n1],     W1[(k0 + 2 * t + 1) * HH + n1]);
        v.w = f2h2(W1[(k0 + 2 * t + 8) * HH + n1], W1[(k0 + 2 * t + 9) * HH + n1]);
        Bp[i] = v;
    }
    if (tid < HH) { b1s[tid] = b1[tid]; w2s[tid] = W2[tid]; }
    const float b2v = b2[0];

    // ================= Grid barrier (ticket-based, replay-safe) =================
    __threadfence();          // prep STGs visible GPU-wide before arrive
    __syncthreads();          // whole block done with prep + staging
    if (tid == 0) {
        const unsigned ticket = atomicAdd(&g_bar_ctr, 1u);
        const unsigned target = (ticket / MAIN_GRID + 1u) * MAIN_GRID;
        unsigned v;
        do {
            asm volatile("ld.acquire.gpu.b32 %0, [%1];"
                         : "=r"(v) : "l"(&g_bar_ctr) : "memory");
        } while (v < target);
    }
    __syncthreads();          // release block; also orders staging STS

    // ================= Phase 2: fused gather + GEMM + epilogue =================
    const int* srcI = eidx;
    const int* dstI = eidx + EE;
    const char* t1b = (const char*)g_v1h;
    const char* t2b = (const char*)g_v2h;
    const unsigned laneOff = (unsigned)lane * 8u;

    for (int tile = blockIdx.x; tile < NTILES; tile += MAIN_GRID) {
        const int e0 = tile * TILE;

        // ---- Gather own 16 edges into As rows [wb, wb+16) (exchange-free) ----
        {
            int eS = e0 + wb + lw;
            if (eS >= EE) eS = EE - 1;            // tail: duplicate, discarded
            // shfl pre-multiplied byte offsets (node*256 < 2^25, fits u32)
            const unsigned myOff =
                (unsigned)((lane < 16) ? srcI[eS] : dstI[eS]) * 256u;
            #pragma unroll
            for (int i = 0; i < 16; i++) {
                const unsigned so = __shfl_sync(0xffffffffu, myOff, i);
                const unsigned dofs = __shfl_sync(0xffffffffu, myOff, 16 + i);
                const uint2 a = *(const uint2*)(t1b + so + laneOff);
                const uint2 b = *(const uint2*)(t2b + dofs + laneOff);
                uint2 p;
                asm("mul.rn.f16x2 %0, %1, %2;" : "=r"(p.x) : "r"(a.x), "r"(b.x));
                asm("mul.rn.f16x2 %0, %1, %2;" : "=r"(p.y) : "r"(a.y), "r"(b.y));
                *(uint2*)(Au + (wb + i) * APW + lane * 2) = p;   // STS.64
            }
        }
        asm volatile("bar.sync %0, %1;" :: "r"(barid), "r"(64) : "memory");

        // ---- GEMM: rows [pb, pb+32), n-half nhalf; B reused across 2 m-tiles ----
        float acc[2][4][4];
        #pragma unroll
        for (int mt = 0; mt < 2; mt++)
            #pragma unroll
            for (int jj = 0; jj < 4; jj++)
                #pragma unroll
                for (int c = 0; c < 4; c++) acc[mt][jj][c] = 0.f;

        #pragma unroll
        for (int ks = 0; ks < 8; ks++) {
            const uint32_t* ar0 = Au + (pb + gid) * APW + 8 * ks + tig;
            const uint32_t* ar1 = ar0 + 16 * APW;
            const uint32_t a00 = ar0[0], a02 = ar0[4];
            const uint32_t a01 = ar0[8 * APW], a03 = ar0[8 * APW + 4];
            const uint32_t a10 = ar1[0], a12 = ar1[4];
            const uint32_t a11 = ar1[8 * APW], a13 = ar1[8 * APW + 4];
            const uint4 bf0 = Bp[(ks * 4 + 2 * nhalf) * 32 + lane];
            const uint4 bf1 = Bp[(ks * 4 + 2 * nhalf + 1) * 32 + lane];
            mma_f16(acc[0][0], a00, a01, a02, a03, bf0.x, bf0.y);
            mma_f16(acc[0][1], a00, a01, a02, a03, bf0.z, bf0.w);
            mma_f16(acc[0][2], a00, a01, a02, a03, bf1.x, bf1.y);
            mma_f16(acc[0][3], a00, a01, a02, a03, bf1.z, bf1.w);
            mma_f16(acc[1][0], a10, a11, a12, a13, bf0.x, bf0.y);
            mma_f16(acc[1][1], a10, a11, a12, a13, bf0.z, bf0.w);
            mma_f16(acc[1][2], a10, a11, a12, a13, bf1.x, bf1.y);
            mma_f16(acc[1][3], a10, a11, a12, a13, bf1.z, bf1.w);
        }

        // ---- Epilogue: bias + ELU + dot(W2) over this warp's 32 n's ----
        #pragma unroll
        for (int mt = 0; mt < 2; mt++) {
            float p0 = 0.f, p1 = 0.f;
            #pragma unroll
            for (int jj = 0; jj < 4; jj++) {
                const int n = (nhalf * 4 + jj) * 8 + 2 * tig;
                const float bb0 = b1s[n], bb1 = b1s[n + 1];
                const float ww0 = w2s[n], ww1 = w2s[n + 1];
                float x;
                x = acc[mt][jj][0] + bb0; p0 = fmaf(x > 0.f ? x : (__expf(x) - 1.f), ww0, p0);
                x = acc[mt][jj][1] + bb1; p0 = fmaf(x > 0.f ? x : (__expf(x) - 1.f), ww1, p0);
                x = acc[mt][jj][2] + bb0; p1 = fmaf(x > 0.f ? x : (__expf(x) - 1.f), ww0, p1);
                x = acc[mt][jj][3] + bb1; p1 = fmaf(x > 0.f ? x : (__expf(x) - 1.f), ww1, p1);
            }
            p0 += __shfl_xor_sync(0xffffffffu, p0, 1);
            p0 += __shfl_xor_sync(0xffffffffu, p0, 2);
            p1 += __shfl_xor_sync(0xffffffffu, p1, 1);
            p1 += __shfl_xor_sync(0xffffffffu, p1, 2);
            if (tig == 0) {
                red[warp * 32 + mt * 16 + gid]     = p0;
                red[warp * 32 + mt * 16 + gid + 8] = p1;
            }
        }
        asm volatile("bar.sync %0, %1;" :: "r"(barid), "r"(64) : "memory");

        // ---- Finalize: each warp of the pair outputs 16 of the 32 edges ----
        if (lane < 16) {
            const int el = nhalf * 16 + lane;
            const float s = red[(pair * 2) * 32 + el] + red[(pair * 2 + 1) * 32 + el] + b2v;
            const int e = e0 + pb + el;
            if (e < EE) out[e] = 1.0f / (1.0f + __expf(-s));
        }
        // next gather's As writes are ordered by the post-gather bar.sync
    }
}

extern "C" void kernel_launch(void* const* d_in, const int* in_sizes, int n_in,
                              void* d_out, int out_size) {
    const float* z_in   = (const float*)d_in[0];
    const float* z_out  = (const float*)d_in[1];
    const float* z_self = (const float*)d_in[2];
    const int*   eidx   = (const int*)d_in[3];
    const float* W1     = (const float*)d_in[4];
    const float* b1     = (const float*)d_in[5];
    const float* W2     = (const float*)d_in[6];
    const float* b2     = (const float*)d_in[7];
    float*       outp   = (float*)d_out;

    const int smem_bytes = SMEM_FLOATS * (int)sizeof(float);   // 52736
    cudaFuncSetAttribute(fused_kernel,
                         cudaFuncAttributeMaxDynamicSharedMemorySize, smem_bytes);
    fused_kernel<<<MAIN_GRID, MAIN_THREADS, smem_bytes>>>(
        z_in, z_out, z_self, eidx, W1, b1, W2, b2, outp);
}

// round 11
// speedup vs baseline: 1.1127x; 1.1127x over previous
#include <cuda_runtime.h>
#include <cuda_fp16.h>
#include <math.h>
#include <stdint.h>

#define NN 100000
#define CC 128
#define EE 600000
#define HH 64
#define TILE 128
#define NTILES ((EE + TILE - 1) / TILE)   // 4688 (last tile half)
#define MAIN_GRID 608                      // 152 SMs * 4 persistent
#define MAIN_THREADS 256

#define APW 68                  // A pitch in 32-bit words (fp16x2 units): 64 + 4 pad

// SMEM float offsets
#define OFF_A   0               // 128*68 = 8704 words
#define OFF_BP  8704            // packed B frags: 8*4*32 uint4 = 4096 words
#define OFF_B1  12800           // 64
#define OFF_W2  12864           // 64
#define OFF_RED 12928           // 8 warps * 32 partials = 256
#define SMEM_FLOATS 13184       // 52736 bytes -> 4 blocks/SM (211KB)

// Node tables in fp16: v1 = z_out + z_self, v2 = z_in + z_self (25.6 MB each).
__device__ uint4 g_v1h[(size_t)NN * CC / 8];
__device__ uint4 g_v2h[(size_t)NN * CC / 8];

__device__ __forceinline__ uint32_t f2h2(float lo, float hi) {
    uint32_t r;
    asm("cvt.rn.f16x2.f32 %0, %1, %2;" : "=r"(r) : "f"(hi), "f"(lo));
    return r;
}

__global__ void prep_kernel(const float* __restrict__ z_in,
                            const float* __restrict__ z_out,
                            const float* __restrict__ z_self) {
    const int i = blockIdx.x * blockDim.x + threadIdx.x;   // 8 channels / thread
    const float4* zi = (const float4*)z_in;
    const float4* zo = (const float4*)z_out;
    const float4* zs = (const float4*)z_self;
    const float4 s0 = zs[2 * i],     s1 = zs[2 * i + 1];
    const float4 a0 = zo[2 * i],     a1 = zo[2 * i + 1];
    const float4 b0 = zi[2 * i],     b1 = zi[2 * i + 1];
    uint4 o1, o2;
    o1.x = f2h2(a0.x + s0.x, a0.y + s0.y);
    o1.y = f2h2(a0.z + s0.z, a0.w + s0.w);
    o1.z = f2h2(a1.x + s1.x, a1.y + s1.y);
    o1.w = f2h2(a1.z + s1.z, a1.w + s1.w);
    o2.x = f2h2(b0.x + s0.x, b0.y + s0.y);
    o2.y = f2h2(b0.z + s0.z, b0.w + s0.w);
    o2.z = f2h2(b1.x + s1.x, b1.y + s1.y);
    o2.w = f2h2(b1.z + s1.z, b1.w + s1.w);
    g_v1h[i] = o1;
    g_v2h[i] = o2;
}

__device__ __forceinline__ uint32_t smem_u32(const void* p) {
    uint32_t a;
    asm("{ .reg .u64 t; cvta.to.shared.u64 t, %1; cvt.u32.u64 %0, t; }" : "=r"(a) : "l"(p));
    return a;
}

__device__ __forceinline__ void mma_f16(float* c,
                                        uint32_t a0, uint32_t a1, uint32_t a2, uint32_t a3,
                                        uint32_t b0, uint32_t b1) {
    asm volatile(
        "mma.sync.aligned.m16n8k16.row.col.f32.f16.f16.f32 "
        "{%0,%1,%2,%3}, {%4,%5,%6,%7}, {%8,%9}, {%0,%1,%2,%3};"
        : "+f"(c[0]), "+f"(c[1]), "+f"(c[2]), "+f"(c[3])
        : "r"(a0), "r"(a1), "r"(a2), "r"(a3), "r"(b0), "r"(b1));
}

__device__ __forceinline__ void ldsm_x4(uint32_t& r0, uint32_t& r1, uint32_t& r2, uint32_t& r3,
                                        uint32_t addr) {
    asm volatile("ldmatrix.sync.aligned.m8n8.x4.shared.b16 {%0,%1,%2,%3}, [%4];"
                 : "=r"(r0), "=r"(r1), "=r"(r2), "=r"(r3) : "r"(addr));
}

// Fused gather + GEMM (fp16 mma.sync) + ELU + GEMV + sigmoid.
// Gather: 2 edges per iteration, LDG.128 per table per lane, exchange-free.
// A fragments via ldmatrix.x4 (1 inst replaces 4 LDS.32).
// Warp PAIRS share 32 edges; each warp covers half of N and both m16 tiles.
__global__ __launch_bounds__(MAIN_THREADS, 4)
void gemm_kernel(const int* __restrict__ eidx,
                 const float* __restrict__ W1,
                 const float* __restrict__ b1,
                 const float* __restrict__ W2,
                 const float* __restrict__ b2,
                 float* __restrict__ out)
{
    extern __shared__ float smem[];
    uint32_t* Au  = (uint32_t*)(smem + OFF_A);
    uint4*    Bp  = (uint4*)(smem + OFF_BP);
    float*    b1s = smem + OFF_B1;
    float*    w2s = smem + OFF_W2;
    float*    red = smem + OFF_RED;

    const int tid   = threadIdx.x;
    const int lane  = tid & 31;
    const int warp  = tid >> 5;
    const int gid   = lane >> 2;   // 0..7
    const int tig   = lane & 3;    // 0..3
    const int wb    = warp * 16;   // gather row base (16 edges per warp)
    const int lw    = lane & 15;
    const int hi    = lane >> 4;   // 0: edge 2i / k-lo, 1: edge 2i+1 / k-hi
    const int pair  = warp >> 1;   // 0..3
    const int nhalf = warp & 1;    // n-half: 0 -> cols 0..31, 1 -> 32..63
    const int pb    = pair * 32;   // pair's edge-row base within tile
    const int barid = pair + 1;

    // ---- Stage packed-B frags (fp16) + vectors, once per persistent block ----
    for (int i = tid; i < 8 * 4 * 32; i += MAIN_THREADS) {
        const int l   = i & 31;
        const int nt2 = (i >> 5) & 3;
        const int ks  = i >> 7;
        const int g   = l >> 2;
        const int t   = l & 3;
        const int k0  = ks * 16;
        const int n0  = nt2 * 16 + g;
        const int n1  = n0 + 8;
        uint4 v;
        v.x = f2h2(W1[(k0 + 2 * t) * HH + n0],     W1[(k0 + 2 * t + 1) * HH + n0]);
        v.y = f2h2(W1[(k0 + 2 * t + 8) * HH + n0], W1[(k0 + 2 * t + 9) * HH + n0]);
        v.z = f2h2(W1[(k0 + 2 * t) * HH + n1],     W1[(k0 + 2 * t + 1) * HH + n1]);
        v.w = f2h2(W1[(k0 + 2 * t + 8) * HH + n1], W1[(k0 + 2 * t + 9) * HH + n1]);
        Bp[i] = v;
    }
    if (tid < HH) { b1s[tid] = b1[tid]; w2s[tid] = W2[tid]; }
    const float b2v = b2[0];
    __syncthreads();

    const int* srcI = eidx;
    const int* dstI = eidx + EE;
    const char* t1b = (const char*)g_v1h;
    const char* t2b = (const char*)g_v2h;
    const unsigned lby = (unsigned)lw * 16u;       // byte offset within node row

    // ldmatrix lane addresses for this warp's two m16 tiles (k-chunk 0)
    const uint32_t sbA = smem_u32(smem);           // OFF_A == 0
    const uint32_t la0 = sbA + (uint32_t)(((pb + lw) * APW + hi * 4) * 4);
    const uint32_t la1 = la0 + 16u * APW * 4u;

    for (int tile = blockIdx.x; tile < NTILES; tile += MAIN_GRID) {
        const int e0 = tile * TILE;

        // ---- Gather own 16 edges (2 per iter) into As rows [wb, wb+16) ----
        {
            int eS = e0 + wb + lw;
            if (eS >= EE) eS = EE - 1;            // tail: duplicate, discarded
            const unsigned myOff =
                (unsigned)((lane < 16) ? srcI[eS] : dstI[eS]) * 256u;
            #pragma unroll
            for (int i = 0; i < 8; i++) {
                const unsigned s0 = __shfl_sync(0xffffffffu, myOff, 2 * i);
                const unsigned s1 = __shfl_sync(0xffffffffu, myOff, 2 * i + 1);
                const unsigned d0 = __shfl_sync(0xffffffffu, myOff, 16 + 2 * i);
                const unsigned d1 = __shfl_sync(0xffffffffu, myOff, 17 + 2 * i);
                const unsigned so = (hi ? s1 : s0) + lby;
                const unsigned dofs = (hi ? d1 : d0) + lby;
                const uint4 a = *(const uint4*)(t1b + so);
                const uint4 b = *(const uint4*)(t2b + dofs);
                uint4 p;
                asm("mul.rn.f16x2 %0, %1, %2;" : "=r"(p.x) : "r"(a.x), "r"(b.x));
                asm("mul.rn.f16x2 %0, %1, %2;" : "=r"(p.y) : "r"(a.y), "r"(b.y));
                asm("mul.rn.f16x2 %0, %1, %2;" : "=r"(p.z) : "r"(a.z), "r"(b.z));
                asm("mul.rn.f16x2 %0, %1, %2;" : "=r"(p.w) : "r"(a.w), "r"(b.w));
                *(uint4*)(Au + (wb + 2 * i + hi) * APW + lw * 4) = p;   // STS.128
            }
        }
        asm volatile("bar.sync %0, %1;" :: "r"(barid), "r"(64) : "memory");

        // ---- GEMM: rows [pb, pb+32), n-half nhalf; A via ldmatrix.x4 ----
        float acc[2][4][4];
        #pragma unroll
        for (int mt = 0; mt < 2; mt++)
            #pragma unroll
            for (int jj = 0; jj < 4; jj++)
                #pragma unroll
                for (int c = 0; c < 4; c++) acc[mt][jj][c] = 0.f;

        #pragma unroll
        for (int ks = 0; ks < 8; ks++) {
            uint32_t a00, a01, a02, a03, a10, a11, a12, a13;
            ldsm_x4(a00, a01, a02, a03, la0 + (uint32_t)(ks * 32));
            ldsm_x4(a10, a11, a12, a13, la1 + (uint32_t)(ks * 32));
            const uint4 bf0 = Bp[(ks * 4 + 2 * nhalf) * 32 + lane];
            const uint4 bf1 = Bp[(ks * 4 + 2 * nhalf + 1) * 32 + lane];
            mma_f16(acc[0][0], a00, a01, a02, a03, bf0.x, bf0.y);
            mma_f16(acc[0][1], a00, a01, a02, a03, bf0.z, bf0.w);
            mma_f16(acc[0][2], a00, a01, a02, a03, bf1.x, bf1.y);
            mma_f16(acc[0][3], a00, a01, a02, a03, bf1.z, bf1.w);
            mma_f16(acc[1][0], a10, a11, a12, a13, bf0.x, bf0.y);
            mma_f16(acc[1][1], a10, a11, a12, a13, bf0.z, bf0.w);
            mma_f16(acc[1][2], a10, a11, a12, a13, bf1.x, bf1.y);
            mma_f16(acc[1][3], a10, a11, a12, a13, bf1.z, bf1.w);
        }

        // ---- Epilogue: bias + ELU + dot(W2) over this warp's 32 n's ----
        #pragma unroll
        for (int mt = 0; mt < 2; mt++) {
            float p0 = 0.f, p1 = 0.f;
            #pragma unroll
            for (int jj = 0; jj < 4; jj++) {
                const int n = (nhalf * 4 + jj) * 8 + 2 * tig;
                const float bb0 = b1s[n], bb1 = b1s[n + 1];
                const float ww0 = w2s[n], ww1 = w2s[n + 1];
                float x;
                x = acc[mt][jj][0] + bb0; p0 = fmaf(x > 0.f ? x : (__expf(x) - 1.f), ww0, p0);
                x = acc[mt][jj][1] + bb1; p0 = fmaf(x > 0.f ? x : (__expf(x) - 1.f), ww1, p0);
                x = acc[mt][jj][2] + bb0; p1 = fmaf(x > 0.f ? x : (__expf(x) - 1.f), ww0, p1);
                x = acc[mt][jj][3] + bb1; p1 = fmaf(x > 0.f ? x : (__expf(x) - 1.f), ww1, p1);
            }
            p0 += __shfl_xor_sync(0xffffffffu, p0, 1);
            p0 += __shfl_xor_sync(0xffffffffu, p0, 2);
            p1 += __shfl_xor_sync(0xffffffffu, p1, 1);
            p1 += __shfl_xor_sync(0xffffffffu, p1, 2);
            if (tig == 0) {
                red[warp * 32 + mt * 16 + gid]     = p0;
                red[warp * 32 + mt * 16 + gid + 8] = p1;
            }
        }
        asm volatile("bar.sync %0, %1;" :: "r"(barid), "r"(64) : "memory");

        // ---- Finalize: each warp of the pair outputs 16 of the 32 edges ----
        if (lane < 16) {
            const int el = nhalf * 16 + lane;
            const float s = red[(pair * 2) * 32 + el] + red[(pair * 2 + 1) * 32 + el] + b2v;
            const int e = e0 + pb + el;
            if (e < EE) out[e] = 1.0f / (1.0f + __expf(-s));
        }
        // next gather's As writes are ordered by the post-gather bar.sync
    }
}

extern "C" void kernel_launch(void* const* d_in, const int* in_sizes, int n_in,
                              void* d_out, int out_size) {
    const float* z_in   = (const float*)d_in[0];
    const float* z_out  = (const float*)d_in[1];
    const float* z_self = (const float*)d_in[2];
    const int*   eidx   = (const int*)d_in[3];
    const float* W1     = (const float*)d_in[4];
    const float* b1     = (const float*)d_in[5];
    const float* W2     = (const float*)d_in[6];
    const float* b2     = (const float*)d_in[7];
    float*       outp   = (float*)d_out;

    prep_kernel<<<NN * CC / 8 / 256, 256>>>(z_in, z_out, z_self);

    const int smem_bytes = SMEM_FLOATS * (int)sizeof(float);   // 52736
    cudaFuncSetAttribute(gemm_kernel,
                         cudaFuncAttributeMaxDynamicSharedMemorySize, smem_bytes);
    gemm_kernel<<<MAIN_GRID, MAIN_THREADS, smem_bytes>>>(eidx, W1, b1, W2, b2, outp);
}